// round 8
// baseline (speedup 1.0000x reference)
#include <cuda_runtime.h>
#include <cstdint>

#define BB 32
#define SS 1024
#define II 128
#define HH 128
#define DD 256   // 2*HH

// ---------------- scratch (static device arrays; allocation-free) -------------
__device__ float g_xg[(size_t)2 * BB * SS * 4 * HH];   // [dir][b][s][4H]
__device__ float g_h [(size_t)BB * SS * DD];           // [b][s][2H] (tf32-rounded)
__device__ float g_qk[(size_t)2 * BB * SS * DD];       // q;k  (D-dim PERMUTED)
__device__ float g_v [(size_t)BB * SS * DD];           // vT [b][d][t] (t PERMUTED)
__device__ float g_sc[(size_t)BB * SS * SS];           // [b][s][t] (t PERMUTED)
// staged weights for merged launches
__device__ float g_wqk[(size_t)2 * DD * DD];           // Wq ; Wk
__device__ float g_wih[(size_t)2 * 4 * HH * II];       // fwWih ; bwWih
__device__ float g_b1 [2 * 4 * HH];
__device__ float g_b2 [2 * 4 * HH];

// ============================ mma.sync tf32 GEMM =============================
// C[M,N] = alpha * A[M,K] @ B[N,K]^T (+ b1 + b2), fp32 I/O, tf32 compute.
// CTA tile 128x128, 8 warps (2M x 4N), warp tile 64x32, mma m16n8k8.
// 3-stage cp.async pipeline, K chunk 32.
// PA/PB: operand stored with octet-permuted k (frag pair adjacent -> LDS.64)
// PC:    write C with octet-permuted columns.  perm: k -> (k&3)*2 + (k>>2)
// =============================================================================
#define GP 36
#define STG_F (128 * GP)
#define NSTG 3
#define GEMM_SMEM ((2 * NSTG * STG_F + 128) * 4)   // ~111KB

__device__ __forceinline__ uint32_t smem_u32(const void* p) {
    uint32_t a;
    asm("{ .reg .u64 t; cvta.to.shared.u64 t, %1; cvt.u32.u64 %0, t; }"
        : "=r"(a) : "l"(p));
    return a;
}
__device__ __forceinline__ void cp16(uint32_t s, const void* g) {
    asm volatile("cp.async.cg.shared.global [%0], [%1], 16;" :: "r"(s), "l"(g));
}
#define CP_COMMIT() asm volatile("cp.async.commit_group;" ::: "memory")
#define CP_WAIT1()  asm volatile("cp.async.wait_group 1;" ::: "memory")
#define CP_WAIT0()  asm volatile("cp.async.wait_group 0;" ::: "memory")

__device__ __forceinline__ uint32_t f2tf(float x) {
    uint32_t r;
    asm("cvt.rna.tf32.f32 %0, %1;" : "=r"(r) : "f"(x));
    return r;
}
__device__ __forceinline__ float roundtf(float x) {
    return __uint_as_float(f2tf(x));
}

__device__ __forceinline__ void mma8(float* d, const uint32_t* a,
                                     const uint32_t* b) {
    asm volatile(
        "mma.sync.aligned.m16n8k8.row.col.f32.tf32.tf32.f32 "
        "{%0,%1,%2,%3}, {%4,%5,%6,%7}, {%8,%9}, {%0,%1,%2,%3};"
        : "+f"(d[0]), "+f"(d[1]), "+f"(d[2]), "+f"(d[3])
        : "r"(a[0]), "r"(a[1]), "r"(a[2]), "r"(a[3]), "r"(b[0]), "r"(b[1]));
}

template <bool CVTA, bool CVTB, bool ROUNDC, bool PA, bool PB, bool PC>
__global__ __launch_bounds__(256, 2) void mma_gemm_nt(
    const float* __restrict__ A, long long sA,
    const float* __restrict__ B, long long sB,
    float* __restrict__ C, long long sC,
    int K, int N, float alpha,
    const float* __restrict__ b1, const float* __restrict__ b2, long long sb)
{
    extern __shared__ float sm[];
    float* AsBase = sm;
    float* BsBase = sm + NSTG * STG_F;
    float* bias   = sm + 2 * NSTG * STG_F;
    const uint32_t smb = smem_u32(sm);

    const int tid  = threadIdx.x;
    const int wid  = tid >> 5, lane = tid & 31;
    const int wm   = wid >> 2, wn = wid & 3;
    const int g    = lane >> 2, tg = lane & 3;

    A += (size_t)blockIdx.z * sA;
    B += (size_t)blockIdx.z * sB;
    C += (size_t)blockIdx.z * sC;
    const int bm = blockIdx.y * 128;
    const int bn = blockIdx.x * 128;

    if (tid < 128) {
        float v = 0.f;
        if (b1) v += b1[blockIdx.z * sb + bn + tid];
        if (b2) v += b2[blockIdx.z * sb + bn + tid];
        bias[tid] = v;
    }

    const int lr = tid >> 3;
    const int c4 = tid & 7;
    const float* Ag0 = A + (size_t)bm * K + c4 * 4;
    const float* Bg0 = B + (size_t)bn * K + c4 * 4;

#define LOADCH(ch, st) do {                                                  \
        const uint32_t abase = smb + (uint32_t)(st) * (STG_F * 4);           \
        const uint32_t bbase = smb + (uint32_t)(NSTG + (st)) * (STG_F * 4);  \
        const float* Ac = Ag0 + (ch) * 32;                                   \
        const float* Bc = Bg0 + (ch) * 32;                                   \
        _Pragma("unroll")                                                    \
        for (int i = 0; i < 4; i++) {                                        \
            const int row = lr + 32 * i;                                     \
            const uint32_t off = (uint32_t)(row * GP + c4 * 4) * 4;          \
            cp16(abase + off, Ac + (size_t)row * K);                         \
            cp16(bbase + off, Bc + (size_t)row * K);                         \
        } } while (0)

    float acc[4][4][4];
#pragma unroll
    for (int mt = 0; mt < 4; mt++)
#pragma unroll
        for (int nt = 0; nt < 4; nt++)
#pragma unroll
            for (int e = 0; e < 4; e++) acc[mt][nt][e] = 0.f;

    const int nch = K >> 5;
    LOADCH(0, 0); CP_COMMIT();
    LOADCH(1, 1); CP_COMMIT();

    for (int i = 0; i < nch; i++) {
        const int s = i % 3;
        if (i + 2 < nch) CP_WAIT1(); else CP_WAIT0();
        __syncthreads();
        if (i + 2 < nch) { LOADCH(i + 2, (i + 2) % 3); CP_COMMIT(); }

        const float* As = AsBase + s * STG_F;
        const float* Bs = BsBase + s * STG_F;
        const uint32_t* Asu = (const uint32_t*)As;
        const uint32_t* Bsu = (const uint32_t*)Bs;
#pragma unroll
        for (int ks = 0; ks < 4; ks++) {
            uint32_t af[4][4], bf[4][2];
#pragma unroll
            for (int mt = 0; mt < 4; mt++) {
                if (PA) {
                    // permuted operand: (tg, tg+4) at positions (2tg, 2tg+1)
                    const int r = (wm * 64 + mt * 16 + g) * GP + ks * 8 + 2 * tg;
                    float2 lo = *(const float2*)&As[r];
                    float2 hi = *(const float2*)&As[r + 8 * GP];
                    af[mt][0] = __float_as_uint(lo.x);
                    af[mt][1] = __float_as_uint(hi.x);
                    af[mt][2] = __float_as_uint(lo.y);
                    af[mt][3] = __float_as_uint(hi.y);
                } else {
                    const int r = (wm * 64 + mt * 16 + g) * GP + ks * 8 + tg;
                    if (CVTA) {
                        af[mt][0] = f2tf(As[r]);
                        af[mt][1] = f2tf(As[r + 8 * GP]);
                        af[mt][2] = f2tf(As[r + 4]);
                        af[mt][3] = f2tf(As[r + 8 * GP + 4]);
                    } else {
                        af[mt][0] = Asu[r];
                        af[mt][1] = Asu[r + 8 * GP];
                        af[mt][2] = Asu[r + 4];
                        af[mt][3] = Asu[r + 8 * GP + 4];
                    }
                }
            }
#pragma unroll
            for (int nt = 0; nt < 4; nt++) {
                if (PB) {
                    const int r = (wn * 32 + nt * 8 + g) * GP + ks * 8 + 2 * tg;
                    float2 bv = *(const float2*)&Bs[r];
                    bf[nt][0] = __float_as_uint(bv.x);
                    bf[nt][1] = __float_as_uint(bv.y);
                } else {
                    const int r = (wn * 32 + nt * 8 + g) * GP + ks * 8 + tg;
                    if (CVTB) {
                        bf[nt][0] = f2tf(Bs[r]);
                        bf[nt][1] = f2tf(Bs[r + 4]);
                    } else {
                        bf[nt][0] = Bsu[r];
                        bf[nt][1] = Bsu[r + 4];
                    }
                }
            }
#pragma unroll
            for (int mt = 0; mt < 4; mt++)
#pragma unroll
                for (int nt = 0; nt < 4; nt++)
                    mma8(acc[mt][nt], af[mt], bf[nt]);
        }
    }
    __syncthreads();

    // epilogue
#pragma unroll
    for (int mt = 0; mt < 4; mt++) {
        const int r0 = bm + wm * 64 + mt * 16 + g;
#pragma unroll
        for (int nt = 0; nt < 4; nt++) {
            const int cl = wn * 32 + nt * 8 + 2 * tg;   // logical col in tile
            float2 o0, o1;
            o0.x = acc[mt][nt][0] * alpha + bias[cl];
            o0.y = acc[mt][nt][1] * alpha + bias[cl + 1];
            o1.x = acc[mt][nt][2] * alpha + bias[cl];
            o1.y = acc[mt][nt][3] * alpha + bias[cl + 1];
            if (ROUNDC) {
                o0.x = roundtf(o0.x); o0.y = roundtf(o0.y);
                o1.x = roundtf(o1.x); o1.y = roundtf(o1.y);
            }
            if (PC) {
                // logical (c, c+1), c = 2tg even -> positions p(c), p(c)+2
                const int w8 = cl & 7;                   // = 2tg
                const int p0 = (cl & ~7) + ((w8 & 3) * 2) + (w8 >> 2);
                const int c0 = bn + p0;
                float* Cr0 = C + (size_t)r0 * N;
                float* Cr1 = C + (size_t)(r0 + 8) * N;
                Cr0[c0] = o0.x; Cr0[c0 + 2] = o0.y;
                Cr1[c0] = o1.x; Cr1[c0 + 2] = o1.y;
            } else {
                const int c0 = bn + cl;
                *(float2*)(C + (size_t)r0 * N + c0)       = o0;
                *(float2*)(C + (size_t)(r0 + 8) * N + c0) = o1;
            }
        }
    }
#undef LOADCH
}

// =============================================================================
// LSTM recurrence (unchanged from R7)
// =============================================================================
#define LSTM_SMEM ((128 + 512) * 4 + 8 * 512 * 16)

__device__ __forceinline__ void fma2(unsigned long long& d,
                                     unsigned long long a,
                                     unsigned long long b)
{
    asm("fma.rn.f32x2 %0, %1, %2, %0;" : "+l"(d) : "l"(a), "l"(b));
}
__device__ __forceinline__ float sum2(unsigned long long a)
{
    return __uint_as_float((unsigned)a) + __uint_as_float((unsigned)(a >> 32));
}
__device__ __forceinline__ float ftanh(float x)
{
    float ax = fabsf(x);
    float e = __expf(2.f * ax);
    float t = 1.f - 2.f / (e + 1.f);
    return copysignf(t, x);
}

__global__ __launch_bounds__(512) void lstm_kernel(
    const float* __restrict__ xg_all,
    const float* __restrict__ Whh_fw,
    const float* __restrict__ Whh_bw,
    float* __restrict__ Hout)
{
    extern __shared__ float sm[];
    float* h_sh = sm;
    float* gate = sm + 128;
    ulonglong2* w_shq = (ulonglong2*)(sm + 640);

    const int dir = blockIdx.x >> 5;
    const int b   = blockIdx.x & 31;
    const int g   = threadIdx.x;
    const float* Whh = dir ? Whh_bw : Whh_fw;

    unsigned long long w2[48];
    {
        const unsigned long long* wr =
            (const unsigned long long*)(Whh + (size_t)g * HH);
#pragma unroll
        for (int i = 0; i < 48; i++) w2[i] = wr[i];
    }
    {
        const ulonglong2* wsrc =
            (const ulonglong2*)(Whh + (size_t)g * HH + 96);
#pragma unroll
        for (int j4 = 0; j4 < 8; j4++) w_shq[j4 * 512 + g] = wsrc[j4];
    }
    if (g < HH) h_sh[g] = 0.f;
    float c = 0.f;
    __syncthreads();

    const float* xg = xg_all + ((size_t)dir * BB + b) * SS * (4 * HH);
    float xg_cur = __ldcs(xg + (size_t)(dir ? SS - 1 : 0) * 512 + g);

    const int gtype = g >> 7;

    for (int t = 0; t < SS; t++) {
        const int s = dir ? (SS - 1 - t) : t;
        float acc = xg_cur;
        if (t + 1 < SS) {
            const int sn = dir ? (SS - 2 - t) : (t + 1);
            xg_cur = __ldcs(xg + (size_t)sn * 512 + g);
        }

        unsigned long long a2a = 0ull, a2b = 0ull;
        const ulonglong2* hq = (const ulonglong2*)h_sh;
#pragma unroll
        for (int i = 0; i < 24; i++) {
            ulonglong2 hv = hq[i];
            fma2(a2a, w2[2 * i], hv.x);
            fma2(a2b, w2[2 * i + 1], hv.y);
        }
#pragma unroll
        for (int j4 = 0; j4 < 8; j4++) {
            ulonglong2 wv = w_shq[j4 * 512 + g];
            ulonglong2 hv = hq[24 + j4];
            fma2(a2a, wv.x, hv.x);
            fma2(a2b, wv.y, hv.y);
        }
        acc += sum2(a2a) + sum2(a2b);

        gate[g] = (gtype == 2) ? ftanh(acc)
                               : 1.f / (1.f + __expf(-acc));
        __syncthreads();

        if (g < HH) {
            const float i_ = gate[g];
            const float f_ = gate[HH + g];
            const float g_ = gate[2 * HH + g];
            const float o_ = gate[3 * HH + g];
            c = f_ * c + i_ * g_;
            const float h = o_ * ftanh(c);
            h_sh[g] = h;
            Hout[((size_t)b * SS + s) * DD + dir * HH + g] = roundtf(h);
        }
        __syncthreads();
    }
}

// =============================================================================
// Row softmax (element-wise per row: permutation-invariant, unchanged)
// =============================================================================
__global__ __launch_bounds__(256) void softmax_rows(float* __restrict__ S)
{
    float* row = S + (size_t)blockIdx.x * SS;
    const int t = threadIdx.x;
    __shared__ float red[8];

    float v0 = row[t], v1 = row[t + 256], v2 = row[t + 512], v3 = row[t + 768];

    float m = fmaxf(fmaxf(v0, v1), fmaxf(v2, v3));
#pragma unroll
    for (int o = 16; o > 0; o >>= 1)
        m = fmaxf(m, __shfl_xor_sync(0xffffffffu, m, o));
    if ((t & 31) == 0) red[t >> 5] = m;
    __syncthreads();
    m = fmaxf(fmaxf(fmaxf(red[0], red[1]), fmaxf(red[2], red[3])),
              fmaxf(fmaxf(red[4], red[5]), fmaxf(red[6], red[7])));

    v0 = __expf(v0 - m); v1 = __expf(v1 - m);
    v2 = __expf(v2 - m); v3 = __expf(v3 - m);
    float s = (v0 + v1) + (v2 + v3);
#pragma unroll
    for (int o = 16; o > 0; o >>= 1)
        s += __shfl_xor_sync(0xffffffffu, s, o);
    __syncthreads();
    if ((t & 31) == 0) red[t >> 5] = s;
    __syncthreads();
    s = ((red[0] + red[1]) + (red[2] + red[3])) +
        ((red[4] + red[5]) + (red[6] + red[7]));
    const float inv = 1.f / s;

    row[t]       = roundtf(v0 * inv);
    row[t + 256] = roundtf(v1 * inv);
    row[t + 512] = roundtf(v2 * inv);
    row[t + 768] = roundtf(v3 * inv);
}

// =============================================================================
// launch
// =============================================================================
extern "C" void kernel_launch(void* const* d_in, const int* in_sizes, int n_in,
                              void* d_out, int out_size)
{
    const float* x     = (const float*)d_in[0];
    const float* fwWih = (const float*)d_in[1];
    const float* fwWhh = (const float*)d_in[2];
    const float* fwbih = (const float*)d_in[3];
    const float* fwbhh = (const float*)d_in[4];
    const float* bwWih = (const float*)d_in[5];
    const float* bwWhh = (const float*)d_in[6];
    const float* bwbih = (const float*)d_in[7];
    const float* bwbhh = (const float*)d_in[8];
    const float* Wq    = (const float*)d_in[9];
    const float* Wk    = (const float*)d_in[10];
    const float* Wv    = (const float*)d_in[11];
    float* out = (float*)d_out;

    float *xg, *h, *qk, *v, *sc, *wqk, *wih, *b1s, *b2s;
    cudaGetSymbolAddress((void**)&xg,  g_xg);
    cudaGetSymbolAddress((void**)&h,   g_h);
    cudaGetSymbolAddress((void**)&qk,  g_qk);
    cudaGetSymbolAddress((void**)&v,   g_v);
    cudaGetSymbolAddress((void**)&sc,  g_sc);
    cudaGetSymbolAddress((void**)&wqk, g_wqk);
    cudaGetSymbolAddress((void**)&wih, g_wih);
    cudaGetSymbolAddress((void**)&b1s, g_b1);
    cudaGetSymbolAddress((void**)&b2s, g_b2);

    // every instantiation is a distinct kernel: bless ALL of them
    cudaFuncSetAttribute(mma_gemm_nt<true, true, false, false, false, false>,
                         cudaFuncAttributeMaxDynamicSharedMemorySize, GEMM_SMEM);
    cudaFuncSetAttribute(mma_gemm_nt<false, true, true, false, false, true>,
                         cudaFuncAttributeMaxDynamicSharedMemorySize, GEMM_SMEM);
    cudaFuncSetAttribute(mma_gemm_nt<true, false, true, false, false, true>,
                         cudaFuncAttributeMaxDynamicSharedMemorySize, GEMM_SMEM);
    cudaFuncSetAttribute(mma_gemm_nt<false, false, false, true, true, true>,
                         cudaFuncAttributeMaxDynamicSharedMemorySize, GEMM_SMEM);
    cudaFuncSetAttribute(mma_gemm_nt<false, false, false, true, true, false>,
                         cudaFuncAttributeMaxDynamicSharedMemorySize, GEMM_SMEM);
    cudaFuncSetAttribute(lstm_kernel,
                         cudaFuncAttributeMaxDynamicSharedMemorySize, LSTM_SMEM);

    const long long SD  = (long long)SS * DD;
    const long long SS2 = (long long)SS * SS;
    const long long BSD = (long long)BB * SS * DD;
    const long long WIH = (long long)4 * HH * II;

    cudaMemcpyAsync(wqk,           Wq,    sizeof(float) * DD * DD,
                    cudaMemcpyDeviceToDevice);
    cudaMemcpyAsync(wqk + DD * DD, Wk,    sizeof(float) * DD * DD,
                    cudaMemcpyDeviceToDevice);
    cudaMemcpyAsync(wih,           fwWih, sizeof(float) * WIH,
                    cudaMemcpyDeviceToDevice);
    cudaMemcpyAsync(wih + WIH,     bwWih, sizeof(float) * WIH,
                    cudaMemcpyDeviceToDevice);
    cudaMemcpyAsync(b1s,           fwbih, sizeof(float) * 4 * HH,
                    cudaMemcpyDeviceToDevice);
    cudaMemcpyAsync(b1s + 4 * HH,  bwbih, sizeof(float) * 4 * HH,
                    cudaMemcpyDeviceToDevice);
    cudaMemcpyAsync(b2s,           fwbhh, sizeof(float) * 4 * HH,
                    cudaMemcpyDeviceToDevice);
    cudaMemcpyAsync(b2s + 4 * HH,  bwbhh, sizeof(float) * 4 * HH,
                    cudaMemcpyDeviceToDevice);

    // 1) xg[dir] = x @ Wih[dir]^T + biases   (merged fw/bw, standard layout)
    mma_gemm_nt<true, true, false, false, false, false>
        <<<dim3(4, 256, 2), 256, GEMM_SMEM>>>(
        x, 0, wih, WIH, xg, (long long)BB * SS * 4 * HH,
        II, 4 * HH, 1.f, b1s, b2s, 4 * HH);

    // 2) bidirectional LSTM recurrence -> h [B,S,2H]
    lstm_kernel<<<64, 512, LSTM_SMEM>>>(xg, fwWhh, bwWhh, h);

    // 3) q,k projections merged (z=2): C permuted on D
    mma_gemm_nt<false, true, true, false, false, true>
        <<<dim3(2, 256, 2), 256, GEMM_SMEM>>>(
        h, 0, wqk, (long long)DD * DD, qk, BSD, DD, DD, 1.f,
        nullptr, nullptr, 0);

    // 3b) vT = Wv @ h^T: C permuted on t
    mma_gemm_nt<true, false, true, false, false, true>
        <<<dim3(8, 2, 32), 256, GEMM_SMEM>>>(
        Wv, 0, h, SD, v, SD, DD, SS, 1.f, nullptr, nullptr, 0);

    // 4) scores = q @ k^T / 16: A,B permuted on D; C permuted on t
    mma_gemm_nt<false, false, false, true, true, true>
        <<<dim3(8, 8, 32), 256, GEMM_SMEM>>>(
        qk, SD, qk + BSD, SD, sc, SS2, DD, SS, 0.0625f, nullptr, nullptr, 0);

    // 5) softmax (permutation-invariant; rounds output)
    softmax_rows<<<BB * SS, 256>>>(sc);

    // 6) out = att @ vT^T: A,B permuted on t; C standard (final output)
    mma_gemm_nt<false, false, false, true, true, false>
        <<<dim3(2, 8, 32), 256, GEMM_SMEM>>>(
        sc, SS2, v, SD, out, SD, SS, DD, 1.f, nullptr, nullptr, 0);
}

// round 9
// speedup vs baseline: 1.0255x; 1.0255x over previous
#include <cuda_runtime.h>
#include <cstdint>

#define BB 32
#define SS 1024
#define II 128
#define HH 128
#define DD 256   // 2*HH

// ---------------- scratch (static device arrays; allocation-free) -------------
__device__ float g_xg[(size_t)2 * BB * SS * 4 * HH];   // [dir][b][s][4H]
__device__ float g_h [(size_t)BB * SS * DD];           // [b][s][2H] (tf32-rounded)
__device__ float g_qk[(size_t)2 * BB * SS * DD];       // q;k tf32-rounded
__device__ float g_v [(size_t)BB * SS * DD];           // vT [b][d][t] tf32-rounded
__device__ float g_sc[(size_t)BB * SS * SS];           // raw scaled logits
__device__ float2 g_part[(size_t)BB * SS * 8];         // per-row-tile (m, s)
__device__ float2 g_rs  [(size_t)BB * SS];             // per-row (m, 1/l)
// staged weights for merged launches
__device__ float g_wqk[(size_t)2 * DD * DD];
__device__ float g_wih[(size_t)2 * 4 * HH * II];
__device__ float g_b1 [2 * 4 * HH];
__device__ float g_b2 [2 * 4 * HH];

// ============================ mma.sync tf32 GEMM =============================
// C[M,N] = alpha * A[M,K] @ B[N,K]^T (+ b1 + b2), fp32 I/O, tf32 compute.
// CTA tile 128x128, 8 warps (2M x 4N), warp tile 64x32, mma m16n8k8.
// 3-stage cp.async pipeline, K chunk 32.
// PARTIAL: epilogue also emits per-(row, tile) softmax partials (m, sum-exp).
// SMAX:    A-fragments transformed p = exp(x - m) * linv using rowstats.
// =============================================================================
#define GP 36
#define STG_F (128 * GP)
#define NSTG 3
// stages + bias(128) + reduction scratch(1024)
#define GEMM_SMEM ((2 * NSTG * STG_F + 128 + 1024) * 4)   // 115200 B

__device__ __forceinline__ uint32_t smem_u32(const void* p) {
    uint32_t a;
    asm("{ .reg .u64 t; cvta.to.shared.u64 t, %1; cvt.u32.u64 %0, t; }"
        : "=r"(a) : "l"(p));
    return a;
}
__device__ __forceinline__ void cp16(uint32_t s, const void* g) {
    asm volatile("cp.async.cg.shared.global [%0], [%1], 16;" :: "r"(s), "l"(g));
}
#define CP_COMMIT() asm volatile("cp.async.commit_group;" ::: "memory")
#define CP_WAIT1()  asm volatile("cp.async.wait_group 1;" ::: "memory")
#define CP_WAIT0()  asm volatile("cp.async.wait_group 0;" ::: "memory")

__device__ __forceinline__ uint32_t f2tf(float x) {
    uint32_t r;
    asm("cvt.rna.tf32.f32 %0, %1;" : "=r"(r) : "f"(x));
    return r;
}
__device__ __forceinline__ float roundtf(float x) {
    return __uint_as_float(f2tf(x));
}

__device__ __forceinline__ void mma8(float* d, const uint32_t* a,
                                     const uint32_t* b) {
    asm volatile(
        "mma.sync.aligned.m16n8k8.row.col.f32.tf32.tf32.f32 "
        "{%0,%1,%2,%3}, {%4,%5,%6,%7}, {%8,%9}, {%0,%1,%2,%3};"
        : "+f"(d[0]), "+f"(d[1]), "+f"(d[2]), "+f"(d[3])
        : "r"(a[0]), "r"(a[1]), "r"(a[2]), "r"(a[3]), "r"(b[0]), "r"(b[1]));
}

template <bool CVTA, bool CVTB, bool ROUNDC, bool PARTIAL, bool SMAX>
__global__ __launch_bounds__(256, 2) void mma_gemm_nt(
    const float* __restrict__ A, long long sA,
    const float* __restrict__ B, long long sB,
    float* __restrict__ C, long long sC,
    int K, int N, float alpha,
    const float* __restrict__ b1, const float* __restrict__ b2, long long sb,
    float2* __restrict__ part, const float2* __restrict__ rowstats)
{
    extern __shared__ float sm[];
    float* AsBase = sm;
    float* BsBase = sm + NSTG * STG_F;
    float* bias   = sm + 2 * NSTG * STG_F;
    float* redm   = bias + 128;            // [128][4]
    float* reds   = redm + 512;            // [128][4]
    const uint32_t smb = smem_u32(sm);

    const int tid  = threadIdx.x;
    const int wid  = tid >> 5, lane = tid & 31;
    const int wm   = wid >> 2, wn = wid & 3;
    const int g    = lane >> 2, tg = lane & 3;

    A += (size_t)blockIdx.z * sA;
    B += (size_t)blockIdx.z * sB;
    C += (size_t)blockIdx.z * sC;
    const int bm = blockIdx.y * 128;
    const int bn = blockIdx.x * 128;

    if (tid < 128) {
        float v = 0.f;
        if (b1) v += b1[blockIdx.z * sb + bn + tid];
        if (b2) v += b2[blockIdx.z * sb + bn + tid];
        bias[tid] = v;
    }

    // SMAX: preload (m, 1/l) for this thread's 8 row-instances
    float2 rs[4][2];
    if (SMAX) {
        const float2* rsb = rowstats + (size_t)blockIdx.z * SS + bm;
#pragma unroll
        for (int mt = 0; mt < 4; mt++) {
            rs[mt][0] = rsb[wm * 64 + mt * 16 + g];
            rs[mt][1] = rsb[wm * 64 + mt * 16 + g + 8];
        }
    }

    const int lr = tid >> 3;
    const int c4 = tid & 7;
    const float* Ag0 = A + (size_t)bm * K + c4 * 4;
    const float* Bg0 = B + (size_t)bn * K + c4 * 4;

#define LOADCH(ch, st) do {                                                  \
        const uint32_t abase = smb + (uint32_t)(st) * (STG_F * 4);           \
        const uint32_t bbase = smb + (uint32_t)(NSTG + (st)) * (STG_F * 4);  \
        const float* Ac = Ag0 + (ch) * 32;                                   \
        const float* Bc = Bg0 + (ch) * 32;                                   \
        _Pragma("unroll")                                                    \
        for (int i = 0; i < 4; i++) {                                        \
            const int row = lr + 32 * i;                                     \
            const uint32_t off = (uint32_t)(row * GP + c4 * 4) * 4;          \
            cp16(abase + off, Ac + (size_t)row * K);                         \
            cp16(bbase + off, Bc + (size_t)row * K);                         \
        } } while (0)

    float acc[4][4][4];
#pragma unroll
    for (int mt = 0; mt < 4; mt++)
#pragma unroll
        for (int nt = 0; nt < 4; nt++)
#pragma unroll
            for (int e = 0; e < 4; e++) acc[mt][nt][e] = 0.f;

    const int nch = K >> 5;
    LOADCH(0, 0); CP_COMMIT();
    LOADCH(1, 1); CP_COMMIT();

    for (int i = 0; i < nch; i++) {
        const int s = i % 3;
        if (i + 2 < nch) CP_WAIT1(); else CP_WAIT0();
        __syncthreads();
        if (i + 2 < nch) { LOADCH(i + 2, (i + 2) % 3); CP_COMMIT(); }

        const float* As = AsBase + s * STG_F;
        const float* Bs = BsBase + s * STG_F;
        const uint32_t* Asu = (const uint32_t*)As;
        const uint32_t* Bsu = (const uint32_t*)Bs;
#pragma unroll
        for (int ks = 0; ks < 4; ks++) {
            uint32_t af[4][4], bf[4][2];
#pragma unroll
            for (int mt = 0; mt < 4; mt++) {
                const int r = (wm * 64 + mt * 16 + g) * GP + ks * 8 + tg;
                if (SMAX) {
                    af[mt][0] = f2tf(__expf(As[r]          - rs[mt][0].x) * rs[mt][0].y);
                    af[mt][1] = f2tf(__expf(As[r + 8 * GP] - rs[mt][1].x) * rs[mt][1].y);
                    af[mt][2] = f2tf(__expf(As[r + 4]          - rs[mt][0].x) * rs[mt][0].y);
                    af[mt][3] = f2tf(__expf(As[r + 8 * GP + 4] - rs[mt][1].x) * rs[mt][1].y);
                } else if (CVTA) {
                    af[mt][0] = f2tf(As[r]);
                    af[mt][1] = f2tf(As[r + 8 * GP]);
                    af[mt][2] = f2tf(As[r + 4]);
                    af[mt][3] = f2tf(As[r + 8 * GP + 4]);
                } else {
                    af[mt][0] = Asu[r];
                    af[mt][1] = Asu[r + 8 * GP];
                    af[mt][2] = Asu[r + 4];
                    af[mt][3] = Asu[r + 8 * GP + 4];
                }
            }
#pragma unroll
            for (int nt = 0; nt < 4; nt++) {
                const int r = (wn * 32 + nt * 8 + g) * GP + ks * 8 + tg;
                if (CVTB) {
                    bf[nt][0] = f2tf(Bs[r]);
                    bf[nt][1] = f2tf(Bs[r + 4]);
                } else {
                    bf[nt][0] = Bsu[r];
                    bf[nt][1] = Bsu[r + 4];
                }
            }
#pragma unroll
            for (int mt = 0; mt < 4; mt++)
#pragma unroll
                for (int nt = 0; nt < 4; nt++)
                    mma8(acc[mt][nt], af[mt], bf[nt]);
        }
    }
    __syncthreads();

    // ---- standard C store (always) ----
#pragma unroll
    for (int mt = 0; mt < 4; mt++) {
        const int r0 = bm + wm * 64 + mt * 16 + g;
#pragma unroll
        for (int nt = 0; nt < 4; nt++) {
            const int cl = wn * 32 + nt * 8 + 2 * tg;
            const int c0 = bn + cl;
            float2 o0, o1;
            o0.x = acc[mt][nt][0] * alpha + bias[cl];
            o0.y = acc[mt][nt][1] * alpha + bias[cl + 1];
            o1.x = acc[mt][nt][2] * alpha + bias[cl];
            o1.y = acc[mt][nt][3] * alpha + bias[cl + 1];
            if (ROUNDC) {
                o0.x = roundtf(o0.x); o0.y = roundtf(o0.y);
                o1.x = roundtf(o1.x); o1.y = roundtf(o1.y);
            }
            *(float2*)(C + (size_t)r0 * N + c0)       = o0;
            *(float2*)(C + (size_t)(r0 + 8) * N + c0) = o1;
        }
    }

    // ---- softmax partials over this 128x128 tile ----
    if (PARTIAL) {
        // pass 1: per-row tile max
#pragma unroll
        for (int mt = 0; mt < 4; mt++)
#pragma unroll
            for (int h2 = 0; h2 < 2; h2++) {
                float lm = -1e30f;
#pragma unroll
                for (int nt = 0; nt < 4; nt++) {
                    lm = fmaxf(lm, acc[mt][nt][h2 * 2 + 0] * alpha);
                    lm = fmaxf(lm, acc[mt][nt][h2 * 2 + 1] * alpha);
                }
                lm = fmaxf(lm, __shfl_xor_sync(0xffffffffu, lm, 1));
                lm = fmaxf(lm, __shfl_xor_sync(0xffffffffu, lm, 2));
                const int r = wm * 64 + mt * 16 + h2 * 8 + g;
                if (tg == 0) redm[r * 4 + wn] = lm;
            }
        __syncthreads();
        // pass 2: per-row exp-sum against tile max
#pragma unroll
        for (int mt = 0; mt < 4; mt++)
#pragma unroll
            for (int h2 = 0; h2 < 2; h2++) {
                const int r = wm * 64 + mt * 16 + h2 * 8 + g;
                const float m = fmaxf(fmaxf(redm[r * 4 + 0], redm[r * 4 + 1]),
                                      fmaxf(redm[r * 4 + 2], redm[r * 4 + 3]));
                float ls = 0.f;
#pragma unroll
                for (int nt = 0; nt < 4; nt++) {
                    ls += __expf(acc[mt][nt][h2 * 2 + 0] * alpha - m);
                    ls += __expf(acc[mt][nt][h2 * 2 + 1] * alpha - m);
                }
                ls += __shfl_xor_sync(0xffffffffu, ls, 1);
                ls += __shfl_xor_sync(0xffffffffu, ls, 2);
                if (tg == 0) reds[r * 4 + wn] = ls;
            }
        __syncthreads();
        if (wn == 0 && tg == 0) {
#pragma unroll
            for (int mt = 0; mt < 4; mt++)
#pragma unroll
                for (int h2 = 0; h2 < 2; h2++) {
                    const int r = wm * 64 + mt * 16 + h2 * 8 + g;
                    const float m = fmaxf(fmaxf(redm[r * 4 + 0], redm[r * 4 + 1]),
                                          fmaxf(redm[r * 4 + 2], redm[r * 4 + 3]));
                    const float s = (reds[r * 4 + 0] + reds[r * 4 + 1]) +
                                    (reds[r * 4 + 2] + reds[r * 4 + 3]);
                    part[((size_t)blockIdx.z * SS + bm + r) * 8 + blockIdx.x] =
                        make_float2(m, s);
                }
        }
    }
#undef LOADCH
}

// =============================================================================
// combine split-softmax partials: (m_j, s_j) x8 -> (m, 1/l) per row
// =============================================================================
__global__ __launch_bounds__(256) void softmax_combine(
    const float2* __restrict__ part, float2* __restrict__ rs)
{
    const int row = blockIdx.x * 256 + threadIdx.x;
    float2 p[8];
    float m = -1e30f;
#pragma unroll
    for (int j = 0; j < 8; j++) {
        p[j] = part[(size_t)row * 8 + j];
        m = fmaxf(m, p[j].x);
    }
    float l = 0.f;
#pragma unroll
    for (int j = 0; j < 8; j++) l += p[j].y * __expf(p[j].x - m);
    rs[row] = make_float2(m, 1.f / l);
}

// =============================================================================
// LSTM recurrence (unchanged from R7)
// =============================================================================
#define LSTM_SMEM ((128 + 512) * 4 + 8 * 512 * 16)

__device__ __forceinline__ void fma2(unsigned long long& d,
                                     unsigned long long a,
                                     unsigned long long b)
{
    asm("fma.rn.f32x2 %0, %1, %2, %0;" : "+l"(d) : "l"(a), "l"(b));
}
__device__ __forceinline__ float sum2(unsigned long long a)
{
    return __uint_as_float((unsigned)a) + __uint_as_float((unsigned)(a >> 32));
}
__device__ __forceinline__ float ftanh(float x)
{
    float ax = fabsf(x);
    float e = __expf(2.f * ax);
    float t = 1.f - 2.f / (e + 1.f);
    return copysignf(t, x);
}

__global__ __launch_bounds__(512) void lstm_kernel(
    const float* __restrict__ xg_all,
    const float* __restrict__ Whh_fw,
    const float* __restrict__ Whh_bw,
    float* __restrict__ Hout)
{
    extern __shared__ float sm[];
    float* h_sh = sm;
    float* gate = sm + 128;
    ulonglong2* w_shq = (ulonglong2*)(sm + 640);

    const int dir = blockIdx.x >> 5;
    const int b   = blockIdx.x & 31;
    const int g   = threadIdx.x;
    const float* Whh = dir ? Whh_bw : Whh_fw;

    unsigned long long w2[48];
    {
        const unsigned long long* wr =
            (const unsigned long long*)(Whh + (size_t)g * HH);
#pragma unroll
        for (int i = 0; i < 48; i++) w2[i] = wr[i];
    }
    {
        const ulonglong2* wsrc =
            (const ulonglong2*)(Whh + (size_t)g * HH + 96);
#pragma unroll
        for (int j4 = 0; j4 < 8; j4++) w_shq[j4 * 512 + g] = wsrc[j4];
    }
    if (g < HH) h_sh[g] = 0.f;
    float c = 0.f;
    __syncthreads();

    const float* xg = xg_all + ((size_t)dir * BB + b) * SS * (4 * HH);
    float xg_cur = __ldcs(xg + (size_t)(dir ? SS - 1 : 0) * 512 + g);

    const int gtype = g >> 7;

    for (int t = 0; t < SS; t++) {
        const int s = dir ? (SS - 1 - t) : t;
        float acc = xg_cur;
        if (t + 1 < SS) {
            const int sn = dir ? (SS - 2 - t) : (t + 1);
            xg_cur = __ldcs(xg + (size_t)sn * 512 + g);
        }

        unsigned long long a2a = 0ull, a2b = 0ull;
        const ulonglong2* hq = (const ulonglong2*)h_sh;
#pragma unroll
        for (int i = 0; i < 24; i++) {
            ulonglong2 hv = hq[i];
            fma2(a2a, w2[2 * i], hv.x);
            fma2(a2b, w2[2 * i + 1], hv.y);
        }
#pragma unroll
        for (int j4 = 0; j4 < 8; j4++) {
            ulonglong2 wv = w_shq[j4 * 512 + g];
            ulonglong2 hv = hq[24 + j4];
            fma2(a2a, wv.x, hv.x);
            fma2(a2b, wv.y, hv.y);
        }
        acc += sum2(a2a) + sum2(a2b);

        gate[g] = (gtype == 2) ? ftanh(acc)
                               : 1.f / (1.f + __expf(-acc));
        __syncthreads();

        if (g < HH) {
            const float i_ = gate[g];
            const float f_ = gate[HH + g];
            const float g_ = gate[2 * HH + g];
            const float o_ = gate[3 * HH + g];
            c = f_ * c + i_ * g_;
            const float h = o_ * ftanh(c);
            h_sh[g] = h;
            Hout[((size_t)b * SS + s) * DD + dir * HH + g] = roundtf(h);
        }
        __syncthreads();
    }
}

// =============================================================================
// launch
// =============================================================================
extern "C" void kernel_launch(void* const* d_in, const int* in_sizes, int n_in,
                              void* d_out, int out_size)
{
    const float* x     = (const float*)d_in[0];
    const float* fwWih = (const float*)d_in[1];
    const float* fwWhh = (const float*)d_in[2];
    const float* fwbih = (const float*)d_in[3];
    const float* fwbhh = (const float*)d_in[4];
    const float* bwWih = (const float*)d_in[5];
    const float* bwWhh = (const float*)d_in[6];
    const float* bwbih = (const float*)d_in[7];
    const float* bwbhh = (const float*)d_in[8];
    const float* Wq    = (const float*)d_in[9];
    const float* Wk    = (const float*)d_in[10];
    const float* Wv    = (const float*)d_in[11];
    float* out = (float*)d_out;

    float *xg, *h, *qk, *v, *sc, *wqk, *wih, *b1s, *b2s;
    float2 *part, *rs;
    cudaGetSymbolAddress((void**)&xg,   g_xg);
    cudaGetSymbolAddress((void**)&h,    g_h);
    cudaGetSymbolAddress((void**)&qk,   g_qk);
    cudaGetSymbolAddress((void**)&v,    g_v);
    cudaGetSymbolAddress((void**)&sc,   g_sc);
    cudaGetSymbolAddress((void**)&part, g_part);
    cudaGetSymbolAddress((void**)&rs,   g_rs);
    cudaGetSymbolAddress((void**)&wqk,  g_wqk);
    cudaGetSymbolAddress((void**)&wih,  g_wih);
    cudaGetSymbolAddress((void**)&b1s,  g_b1);
    cudaGetSymbolAddress((void**)&b2s,  g_b2);

    // every instantiation is a distinct kernel: bless ALL of them
    cudaFuncSetAttribute(mma_gemm_nt<true, true, false, false, false>,
                         cudaFuncAttributeMaxDynamicSharedMemorySize, GEMM_SMEM);
    cudaFuncSetAttribute(mma_gemm_nt<false, true, true, false, false>,
                         cudaFuncAttributeMaxDynamicSharedMemorySize, GEMM_SMEM);
    cudaFuncSetAttribute(mma_gemm_nt<true, false, true, false, false>,
                         cudaFuncAttributeMaxDynamicSharedMemorySize, GEMM_SMEM);
    cudaFuncSetAttribute(mma_gemm_nt<false, false, false, true, false>,
                         cudaFuncAttributeMaxDynamicSharedMemorySize, GEMM_SMEM);
    cudaFuncSetAttribute(mma_gemm_nt<false, false, false, false, true>,
                         cudaFuncAttributeMaxDynamicSharedMemorySize, GEMM_SMEM);
    cudaFuncSetAttribute(lstm_kernel,
                         cudaFuncAttributeMaxDynamicSharedMemorySize, LSTM_SMEM);

    const long long SD  = (long long)SS * DD;
    const long long SS2 = (long long)SS * SS;
    const long long BSD = (long long)BB * SS * DD;
    const long long WIH = (long long)4 * HH * II;

    cudaMemcpyAsync(wqk,           Wq,    sizeof(float) * DD * DD,
                    cudaMemcpyDeviceToDevice);
    cudaMemcpyAsync(wqk + DD * DD, Wk,    sizeof(float) * DD * DD,
                    cudaMemcpyDeviceToDevice);
    cudaMemcpyAsync(wih,           fwWih, sizeof(float) * WIH,
                    cudaMemcpyDeviceToDevice);
    cudaMemcpyAsync(wih + WIH,     bwWih, sizeof(float) * WIH,
                    cudaMemcpyDeviceToDevice);
    cudaMemcpyAsync(b1s,           fwbih, sizeof(float) * 4 * HH,
                    cudaMemcpyDeviceToDevice);
    cudaMemcpyAsync(b1s + 4 * HH,  bwbih, sizeof(float) * 4 * HH,
                    cudaMemcpyDeviceToDevice);
    cudaMemcpyAsync(b2s,           fwbhh, sizeof(float) * 4 * HH,
                    cudaMemcpyDeviceToDevice);
    cudaMemcpyAsync(b2s + 4 * HH,  bwbhh, sizeof(float) * 4 * HH,
                    cudaMemcpyDeviceToDevice);

    // 1) xg[dir] = x @ Wih[dir]^T + biases (merged fw/bw)
    mma_gemm_nt<true, true, false, false, false>
        <<<dim3(4, 256, 2), 256, GEMM_SMEM>>>(
        x, 0, wih, WIH, xg, (long long)BB * SS * 4 * HH,
        II, 4 * HH, 1.f, b1s, b2s, 4 * HH, nullptr, nullptr);

    // 2) bidirectional LSTM recurrence -> h [B,S,2H]
    lstm_kernel<<<64, 512, LSTM_SMEM>>>(xg, fwWhh, bwWhh, h);

    // 3) q,k projections merged (z=2)
    mma_gemm_nt<false, true, true, false, false>
        <<<dim3(2, 256, 2), 256, GEMM_SMEM>>>(
        h, 0, wqk, (long long)DD * DD, qk, BSD, DD, DD, 1.f,
        nullptr, nullptr, 0, nullptr, nullptr);

    // 3b) vT = Wv @ h^T
    mma_gemm_nt<true, false, true, false, false>
        <<<dim3(8, 2, 32), 256, GEMM_SMEM>>>(
        Wv, 0, h, SD, v, SD, DD, SS, 1.f, nullptr, nullptr, 0,
        nullptr, nullptr);

    // 4) scores = q @ k^T / 16, raw logits + per-tile softmax partials
    mma_gemm_nt<false, false, false, true, false>
        <<<dim3(8, 8, 32), 256, GEMM_SMEM>>>(
        qk, SD, qk + BSD, SD, sc, SS2, DD, SS, 0.0625f,
        nullptr, nullptr, 0, part, nullptr);

    // 5) combine partials -> per-row (m, 1/l)
    softmax_combine<<<BB * SS / 256, 256>>>(part, rs);

    // 6) out = softmax(sc) @ vT^T with exp applied at fragment load
    mma_gemm_nt<false, false, false, false, true>
        <<<dim3(2, 8, 32), 256, GEMM_SMEM>>>(
        sc, SS2, v, SD, out, SD, SS, DD, 1.f,
        nullptr, nullptr, 0, nullptr, rs);
}

// round 10
// speedup vs baseline: 1.0527x; 1.0266x over previous
#include <cuda_runtime.h>
#include <cstdint>

#define BB 32
#define SS 1024
#define II 128
#define HH 128
#define DD 256   // 2*HH

// ---------------- scratch (static device arrays; allocation-free) -------------
__device__ float g_xg[(size_t)2 * BB * SS * 4 * HH];   // [dir][b][s][4H]
__device__ float g_h [(size_t)BB * SS * DD];           // [b][s][2H] (tf32-rounded)
__device__ float g_qk[(size_t)2 * BB * SS * DD];       // q;k tf32-rounded
__device__ float g_v [(size_t)BB * SS * DD];           // vT [b][d][t] tf32-rounded
__device__ float g_sc[(size_t)BB * SS * SS];           // exp(x - m_tile) values
__device__ float2 g_part[(size_t)BB * SS * 8];         // per-row-tile (m, s)
__device__ float  g_fac [(size_t)BB * SS * 8];         // per-row-tile exp(m_j-m)/l
// staged weights for merged launches
__device__ float g_wqk[(size_t)2 * DD * DD];
__device__ float g_wih[(size_t)2 * 4 * HH * II];
__device__ float g_b1 [2 * 4 * HH];
__device__ float g_b2 [2 * 4 * HH];

// ============================ mma.sync tf32 GEMM =============================
// C[M,N] = alpha * A[M,K] @ B[N,K]^T (+ b1 + b2), fp32 I/O, tf32 compute.
// CTA tile 128x128, 8 warps (2M x 4N), warp tile 64x32, mma m16n8k8.
// 3-stage cp.async pipeline, K chunk 32.
// PARTIAL: C := exp(alpha*acc - m_tile); emit (m_tile, sum) partials per row.
// SMAX:    A-fragments scaled by per-(row, ktile) factor fac (flash-style).
// =============================================================================
#define GP 36
#define STG_F (128 * GP)
#define NSTG 3
#define GEMM_SMEM ((2 * NSTG * STG_F + 128 + 1024) * 4)   // 115200 B

__device__ __forceinline__ uint32_t smem_u32(const void* p) {
    uint32_t a;
    asm("{ .reg .u64 t; cvta.to.shared.u64 t, %1; cvt.u32.u64 %0, t; }"
        : "=r"(a) : "l"(p));
    return a;
}
__device__ __forceinline__ void cp16(uint32_t s, const void* g) {
    asm volatile("cp.async.cg.shared.global [%0], [%1], 16;" :: "r"(s), "l"(g));
}
#define CP_COMMIT() asm volatile("cp.async.commit_group;" ::: "memory")
#define CP_WAIT1()  asm volatile("cp.async.wait_group 1;" ::: "memory")
#define CP_WAIT0()  asm volatile("cp.async.wait_group 0;" ::: "memory")

__device__ __forceinline__ uint32_t f2tf(float x) {
    uint32_t r;
    asm("cvt.rna.tf32.f32 %0, %1;" : "=r"(r) : "f"(x));
    return r;
}
__device__ __forceinline__ float roundtf(float x) {
    return __uint_as_float(f2tf(x));
}

__device__ __forceinline__ void mma8(float* d, const uint32_t* a,
                                     const uint32_t* b) {
    asm volatile(
        "mma.sync.aligned.m16n8k8.row.col.f32.tf32.tf32.f32 "
        "{%0,%1,%2,%3}, {%4,%5,%6,%7}, {%8,%9}, {%0,%1,%2,%3};"
        : "+f"(d[0]), "+f"(d[1]), "+f"(d[2]), "+f"(d[3])
        : "r"(a[0]), "r"(a[1]), "r"(a[2]), "r"(a[3]), "r"(b[0]), "r"(b[1]));
}

template <bool CVTA, bool CVTB, bool ROUNDC, bool PARTIAL, bool SMAX>
__global__ __launch_bounds__(256, 2) void mma_gemm_nt(
    const float* __restrict__ A, long long sA,
    const float* __restrict__ B, long long sB,
    float* __restrict__ C, long long sC,
    int K, int N, float alpha,
    const float* __restrict__ b1, const float* __restrict__ b2, long long sb,
    float2* __restrict__ part, const float* __restrict__ fac)
{
    extern __shared__ float sm[];
    float* AsBase = sm;
    float* BsBase = sm + NSTG * STG_F;
    float* bias   = sm + 2 * NSTG * STG_F;
    float* redm   = bias + 128;            // [128][4]
    float* reds   = redm + 512;            // [128][4]
    const uint32_t smb = smem_u32(sm);

    const int tid  = threadIdx.x;
    const int wid  = tid >> 5, lane = tid & 31;
    const int wm   = wid >> 2, wn = wid & 3;
    const int g    = lane >> 2, tg = lane & 3;

    A += (size_t)blockIdx.z * sA;
    B += (size_t)blockIdx.z * sB;
    C += (size_t)blockIdx.z * sC;
    const int bm = blockIdx.y * 128;
    const int bn = blockIdx.x * 128;

    if (tid < 128) {
        float v = 0.f;
        if (b1) v += b1[blockIdx.z * sb + bn + tid];
        if (b2) v += b2[blockIdx.z * sb + bn + tid];
        bias[tid] = v;
    }

    // SMAX: fac table base for this CTA's 8 row-instances; double-buffered
    const float* facb = nullptr;
    float facA[4][2], facB[4][2];
    if (SMAX) {
        facb = fac + ((size_t)blockIdx.z * SS + bm) * 8;
#pragma unroll
        for (int mt = 0; mt < 4; mt++) {
            facA[mt][0] = facb[(wm * 64 + mt * 16 + g) * 8];
            facA[mt][1] = facb[(wm * 64 + mt * 16 + g + 8) * 8];
        }
    }

    const int lr = tid >> 3;
    const int c4 = tid & 7;
    const float* Ag0 = A + (size_t)bm * K + c4 * 4;
    const float* Bg0 = B + (size_t)bn * K + c4 * 4;

#define LOADCH(ch, st) do {                                                  \
        const uint32_t abase = smb + (uint32_t)(st) * (STG_F * 4);           \
        const uint32_t bbase = smb + (uint32_t)(NSTG + (st)) * (STG_F * 4);  \
        const float* Ac = Ag0 + (ch) * 32;                                   \
        const float* Bc = Bg0 + (ch) * 32;                                   \
        _Pragma("unroll")                                                    \
        for (int i = 0; i < 4; i++) {                                        \
            const int row = lr + 32 * i;                                     \
            const uint32_t off = (uint32_t)(row * GP + c4 * 4) * 4;          \
            cp16(abase + off, Ac + (size_t)row * K);                         \
            cp16(bbase + off, Bc + (size_t)row * K);                         \
        } } while (0)

    float acc[4][4][4];
#pragma unroll
    for (int mt = 0; mt < 4; mt++)
#pragma unroll
        for (int nt = 0; nt < 4; nt++)
#pragma unroll
            for (int e = 0; e < 4; e++) acc[mt][nt][e] = 0.f;

    const int nch = K >> 5;
    LOADCH(0, 0); CP_COMMIT();
    LOADCH(1, 1); CP_COMMIT();

    for (int i = 0; i < nch; i++) {
        const int s = i % 3;
        if (i + 2 < nch) CP_WAIT1(); else CP_WAIT0();
        __syncthreads();
        if (i + 2 < nch) { LOADCH(i + 2, (i + 2) % 3); CP_COMMIT(); }

        if (SMAX && (i & 3) == 0) {
            if (i) {
#pragma unroll
                for (int mt = 0; mt < 4; mt++) {
                    facA[mt][0] = facB[mt][0];
                    facA[mt][1] = facB[mt][1];
                }
            }
            if (i + 4 < nch) {            // prefetch next ktile's factors
                const float* fp = facb + (i >> 2) + 1;
#pragma unroll
                for (int mt = 0; mt < 4; mt++) {
                    facB[mt][0] = fp[(wm * 64 + mt * 16 + g) * 8];
                    facB[mt][1] = fp[(wm * 64 + mt * 16 + g + 8) * 8];
                }
            }
        }

        const float* As = AsBase + s * STG_F;
        const float* Bs = BsBase + s * STG_F;
        const uint32_t* Asu = (const uint32_t*)As;
        const uint32_t* Bsu = (const uint32_t*)Bs;
#pragma unroll
        for (int ks = 0; ks < 4; ks++) {
            uint32_t af[4][4], bf[4][2];
#pragma unroll
            for (int mt = 0; mt < 4; mt++) {
                const int r = (wm * 64 + mt * 16 + g) * GP + ks * 8 + tg;
                if (SMAX) {
                    af[mt][0] = f2tf(As[r]          * facA[mt][0]);
                    af[mt][1] = f2tf(As[r + 8 * GP] * facA[mt][1]);
                    af[mt][2] = f2tf(As[r + 4]          * facA[mt][0]);
                    af[mt][3] = f2tf(As[r + 8 * GP + 4] * facA[mt][1]);
                } else if (CVTA) {
                    af[mt][0] = f2tf(As[r]);
                    af[mt][1] = f2tf(As[r + 8 * GP]);
                    af[mt][2] = f2tf(As[r + 4]);
                    af[mt][3] = f2tf(As[r + 8 * GP + 4]);
                } else {
                    af[mt][0] = Asu[r];
                    af[mt][1] = Asu[r + 8 * GP];
                    af[mt][2] = Asu[r + 4];
                    af[mt][3] = Asu[r + 8 * GP + 4];
                }
            }
#pragma unroll
            for (int nt = 0; nt < 4; nt++) {
                const int r = (wn * 32 + nt * 8 + g) * GP + ks * 8 + tg;
                if (CVTB) {
                    bf[nt][0] = f2tf(Bs[r]);
                    bf[nt][1] = f2tf(Bs[r + 4]);
                } else {
                    bf[nt][0] = Bsu[r];
                    bf[nt][1] = Bsu[r + 4];
                }
            }
#pragma unroll
            for (int mt = 0; mt < 4; mt++)
#pragma unroll
                for (int nt = 0; nt < 4; nt++)
                    mma8(acc[mt][nt], af[mt], bf[nt]);
        }
    }
    __syncthreads();

    if (!PARTIAL) {
        // ---- standard C store ----
#pragma unroll
        for (int mt = 0; mt < 4; mt++) {
            const int r0 = bm + wm * 64 + mt * 16 + g;
#pragma unroll
            for (int nt = 0; nt < 4; nt++) {
                const int cl = wn * 32 + nt * 8 + 2 * tg;
                const int c0 = bn + cl;
                float2 o0, o1;
                o0.x = acc[mt][nt][0] * alpha + bias[cl];
                o0.y = acc[mt][nt][1] * alpha + bias[cl + 1];
                o1.x = acc[mt][nt][2] * alpha + bias[cl];
                o1.y = acc[mt][nt][3] * alpha + bias[cl + 1];
                if (ROUNDC) {
                    o0.x = roundtf(o0.x); o0.y = roundtf(o0.y);
                    o1.x = roundtf(o1.x); o1.y = roundtf(o1.y);
                }
                *(float2*)(C + (size_t)r0 * N + c0)       = o0;
                *(float2*)(C + (size_t)(r0 + 8) * N + c0) = o1;
            }
        }
    } else {
        // ---- fused softmax-partial epilogue ----
        // pass 1: per-row tile max of alpha*acc
#pragma unroll
        for (int mt = 0; mt < 4; mt++)
#pragma unroll
            for (int h2 = 0; h2 < 2; h2++) {
                float lm = -1e30f;
#pragma unroll
                for (int nt = 0; nt < 4; nt++) {
                    lm = fmaxf(lm, acc[mt][nt][h2 * 2 + 0] * alpha);
                    lm = fmaxf(lm, acc[mt][nt][h2 * 2 + 1] * alpha);
                }
                lm = fmaxf(lm, __shfl_xor_sync(0xffffffffu, lm, 1));
                lm = fmaxf(lm, __shfl_xor_sync(0xffffffffu, lm, 2));
                const int r = wm * 64 + mt * 16 + h2 * 8 + g;
                if (tg == 0) redm[r * 4 + wn] = lm;
            }
        __syncthreads();
        // pass 2: exp against tile max; STORE exp values as C; accumulate sum
#pragma unroll
        for (int mt = 0; mt < 4; mt++)
#pragma unroll
            for (int h2 = 0; h2 < 2; h2++) {
                const int r = wm * 64 + mt * 16 + h2 * 8 + g;
                const float m = fmaxf(fmaxf(redm[r * 4 + 0], redm[r * 4 + 1]),
                                      fmaxf(redm[r * 4 + 2], redm[r * 4 + 3]));
                float* Crow = C + (size_t)(bm + r) * N + bn;
                float ls = 0.f;
#pragma unroll
                for (int nt = 0; nt < 4; nt++) {
                    const int cl = wn * 32 + nt * 8 + 2 * tg;
                    float2 e;
                    e.x = __expf(acc[mt][nt][h2 * 2 + 0] * alpha - m);
                    e.y = __expf(acc[mt][nt][h2 * 2 + 1] * alpha - m);
                    *(float2*)(Crow + cl) = e;
                    ls += e.x + e.y;
                }
                ls += __shfl_xor_sync(0xffffffffu, ls, 1);
                ls += __shfl_xor_sync(0xffffffffu, ls, 2);
                if (tg == 0) reds[r * 4 + wn] = ls;
            }
        __syncthreads();
        if (wn == 0 && tg == 0) {
#pragma unroll
            for (int mt = 0; mt < 4; mt++)
#pragma unroll
                for (int h2 = 0; h2 < 2; h2++) {
                    const int r = wm * 64 + mt * 16 + h2 * 8 + g;
                    const float m = fmaxf(fmaxf(redm[r * 4 + 0], redm[r * 4 + 1]),
                                          fmaxf(redm[r * 4 + 2], redm[r * 4 + 3]));
                    const float s = (reds[r * 4 + 0] + reds[r * 4 + 1]) +
                                    (reds[r * 4 + 2] + reds[r * 4 + 3]);
                    part[((size_t)blockIdx.z * SS + bm + r) * 8 + blockIdx.x] =
                        make_float2(m, s);
                }
        }
    }
#undef LOADCH
}

// =============================================================================
// combine split-softmax partials: (m_j, s_j) x8 -> fac_j = exp(m_j - m)/l
// =============================================================================
__global__ __launch_bounds__(256) void softmax_combine(
    const float2* __restrict__ part, float* __restrict__ fac)
{
    const int row = blockIdx.x * 256 + threadIdx.x;
    float2 p[8];
    float m = -1e30f;
#pragma unroll
    for (int j = 0; j < 8; j++) {
        p[j] = part[(size_t)row * 8 + j];
        m = fmaxf(m, p[j].x);
    }
    float l = 0.f;
    float e[8];
#pragma unroll
    for (int j = 0; j < 8; j++) {
        e[j] = __expf(p[j].x - m);
        l += p[j].y * e[j];
    }
    const float inv = 1.f / l;
#pragma unroll
    for (int j = 0; j < 8; j++) fac[(size_t)row * 8 + j] = e[j] * inv;
}

// =============================================================================
// LSTM recurrence (unchanged from R7)
// =============================================================================
#define LSTM_SMEM ((128 + 512) * 4 + 8 * 512 * 16)

__device__ __forceinline__ void fma2(unsigned long long& d,
                                     unsigned long long a,
                                     unsigned long long b)
{
    asm("fma.rn.f32x2 %0, %1, %2, %0;" : "+l"(d) : "l"(a), "l"(b));
}
__device__ __forceinline__ float sum2(unsigned long long a)
{
    return __uint_as_float((unsigned)a) + __uint_as_float((unsigned)(a >> 32));
}
__device__ __forceinline__ float ftanh(float x)
{
    float ax = fabsf(x);
    float e = __expf(2.f * ax);
    float t = 1.f - 2.f / (e + 1.f);
    return copysignf(t, x);
}

__global__ __launch_bounds__(512) void lstm_kernel(
    const float* __restrict__ xg_all,
    const float* __restrict__ Whh_fw,
    const float* __restrict__ Whh_bw,
    float* __restrict__ Hout)
{
    extern __shared__ float sm[];
    float* h_sh = sm;
    float* gate = sm + 128;
    ulonglong2* w_shq = (ulonglong2*)(sm + 640);

    const int dir = blockIdx.x >> 5;
    const int b   = blockIdx.x & 31;
    const int g   = threadIdx.x;
    const float* Whh = dir ? Whh_bw : Whh_fw;

    unsigned long long w2[48];
    {
        const unsigned long long* wr =
            (const unsigned long long*)(Whh + (size_t)g * HH);
#pragma unroll
        for (int i = 0; i < 48; i++) w2[i] = wr[i];
    }
    {
        const ulonglong2* wsrc =
            (const ulonglong2*)(Whh + (size_t)g * HH + 96);
#pragma unroll
        for (int j4 = 0; j4 < 8; j4++) w_shq[j4 * 512 + g] = wsrc[j4];
    }
    if (g < HH) h_sh[g] = 0.f;
    float c = 0.f;
    __syncthreads();

    const float* xg = xg_all + ((size_t)dir * BB + b) * SS * (4 * HH);
    float xg_cur = __ldcs(xg + (size_t)(dir ? SS - 1 : 0) * 512 + g);

    const int gtype = g >> 7;

    for (int t = 0; t < SS; t++) {
        const int s = dir ? (SS - 1 - t) : t;
        float acc = xg_cur;
        if (t + 1 < SS) {
            const int sn = dir ? (SS - 2 - t) : (t + 1);
            xg_cur = __ldcs(xg + (size_t)sn * 512 + g);
        }

        unsigned long long a2a = 0ull, a2b = 0ull;
        const ulonglong2* hq = (const ulonglong2*)h_sh;
#pragma unroll
        for (int i = 0; i < 24; i++) {
            ulonglong2 hv = hq[i];
            fma2(a2a, w2[2 * i], hv.x);
            fma2(a2b, w2[2 * i + 1], hv.y);
        }
#pragma unroll
        for (int j4 = 0; j4 < 8; j4++) {
            ulonglong2 wv = w_shq[j4 * 512 + g];
            ulonglong2 hv = hq[24 + j4];
            fma2(a2a, wv.x, hv.x);
            fma2(a2b, wv.y, hv.y);
        }
        acc += sum2(a2a) + sum2(a2b);

        gate[g] = (gtype == 2) ? ftanh(acc)
                               : 1.f / (1.f + __expf(-acc));
        __syncthreads();

        if (g < HH) {
            const float i_ = gate[g];
            const float f_ = gate[HH + g];
            const float g_ = gate[2 * HH + g];
            const float o_ = gate[3 * HH + g];
            c = f_ * c + i_ * g_;
            const float h = o_ * ftanh(c);
            h_sh[g] = h;
            Hout[((size_t)b * SS + s) * DD + dir * HH + g] = roundtf(h);
        }
        __syncthreads();
    }
}

// =============================================================================
// launch
// =============================================================================
extern "C" void kernel_launch(void* const* d_in, const int* in_sizes, int n_in,
                              void* d_out, int out_size)
{
    const float* x     = (const float*)d_in[0];
    const float* fwWih = (const float*)d_in[1];
    const float* fwWhh = (const float*)d_in[2];
    const float* fwbih = (const float*)d_in[3];
    const float* fwbhh = (const float*)d_in[4];
    const float* bwWih = (const float*)d_in[5];
    const float* bwWhh = (const float*)d_in[6];
    const float* bwbih = (const float*)d_in[7];
    const float* bwbhh = (const float*)d_in[8];
    const float* Wq    = (const float*)d_in[9];
    const float* Wk    = (const float*)d_in[10];
    const float* Wv    = (const float*)d_in[11];
    float* out = (float*)d_out;

    float *xg, *h, *qk, *v, *sc, *fac, *wqk, *wih, *b1s, *b2s;
    float2 *part;
    cudaGetSymbolAddress((void**)&xg,   g_xg);
    cudaGetSymbolAddress((void**)&h,    g_h);
    cudaGetSymbolAddress((void**)&qk,   g_qk);
    cudaGetSymbolAddress((void**)&v,    g_v);
    cudaGetSymbolAddress((void**)&sc,   g_sc);
    cudaGetSymbolAddress((void**)&part, g_part);
    cudaGetSymbolAddress((void**)&fac,  g_fac);
    cudaGetSymbolAddress((void**)&wqk,  g_wqk);
    cudaGetSymbolAddress((void**)&wih,  g_wih);
    cudaGetSymbolAddress((void**)&b1s,  g_b1);
    cudaGetSymbolAddress((void**)&b2s,  g_b2);

    cudaFuncSetAttribute(mma_gemm_nt<true, true, false, false, false>,
                         cudaFuncAttributeMaxDynamicSharedMemorySize, GEMM_SMEM);
    cudaFuncSetAttribute(mma_gemm_nt<false, true, true, false, false>,
                         cudaFuncAttributeMaxDynamicSharedMemorySize, GEMM_SMEM);
    cudaFuncSetAttribute(mma_gemm_nt<true, false, true, false, false>,
                         cudaFuncAttributeMaxDynamicSharedMemorySize, GEMM_SMEM);
    cudaFuncSetAttribute(mma_gemm_nt<false, false, false, true, false>,
                         cudaFuncAttributeMaxDynamicSharedMemorySize, GEMM_SMEM);
    cudaFuncSetAttribute(mma_gemm_nt<false, false, false, false, true>,
                         cudaFuncAttributeMaxDynamicSharedMemorySize, GEMM_SMEM);
    cudaFuncSetAttribute(lstm_kernel,
                         cudaFuncAttributeMaxDynamicSharedMemorySize, LSTM_SMEM);

    const long long SD  = (long long)SS * DD;
    const long long SS2 = (long long)SS * SS;
    const long long BSD = (long long)BB * SS * DD;
    const long long WIH = (long long)4 * HH * II;

    cudaMemcpyAsync(wqk,           Wq,    sizeof(float) * DD * DD,
                    cudaMemcpyDeviceToDevice);
    cudaMemcpyAsync(wqk + DD * DD, Wk,    sizeof(float) * DD * DD,
                    cudaMemcpyDeviceToDevice);
    cudaMemcpyAsync(wih,           fwWih, sizeof(float) * WIH,
                    cudaMemcpyDeviceToDevice);
    cudaMemcpyAsync(wih + WIH,     bwWih, sizeof(float) * WIH,
                    cudaMemcpyDeviceToDevice);
    cudaMemcpyAsync(b1s,           fwbih, sizeof(float) * 4 * HH,
                    cudaMemcpyDeviceToDevice);
    cudaMemcpyAsync(b1s + 4 * HH,  bwbih, sizeof(float) * 4 * HH,
                    cudaMemcpyDeviceToDevice);
    cudaMemcpyAsync(b2s,           fwbhh, sizeof(float) * 4 * HH,
                    cudaMemcpyDeviceToDevice);
    cudaMemcpyAsync(b2s + 4 * HH,  bwbhh, sizeof(float) * 4 * HH,
                    cudaMemcpyDeviceToDevice);

    // 1) xg[dir] = x @ Wih[dir]^T + biases (merged fw/bw)
    mma_gemm_nt<true, true, false, false, false>
        <<<dim3(4, 256, 2), 256, GEMM_SMEM>>>(
        x, 0, wih, WIH, xg, (long long)BB * SS * 4 * HH,
        II, 4 * HH, 1.f, b1s, b2s, 4 * HH, nullptr, nullptr);

    // 2) bidirectional LSTM recurrence -> h [B,S,2H]
    lstm_kernel<<<64, 512, LSTM_SMEM>>>(xg, fwWhh, bwWhh, h);

    // 3) q,k projections merged (z=2)
    mma_gemm_nt<false, true, true, false, false>
        <<<dim3(2, 256, 2), 256, GEMM_SMEM>>>(
        h, 0, wqk, (long long)DD * DD, qk, BSD, DD, DD, 1.f,
        nullptr, nullptr, 0, nullptr, nullptr);

    // 3b) vT = Wv @ h^T
    mma_gemm_nt<true, false, true, false, false>
        <<<dim3(8, 2, 32), 256, GEMM_SMEM>>>(
        Wv, 0, h, SD, v, SD, DD, SS, 1.f, nullptr, nullptr, 0,
        nullptr, nullptr);

    // 4) scores: C = exp(q@k^T/16 - m_tile), partials (m_tile, s_tile)
    mma_gemm_nt<false, false, false, true, false>
        <<<dim3(8, 8, 32), 256, GEMM_SMEM>>>(
        qk, SD, qk + BSD, SD, sc, SS2, DD, SS, 0.0625f,
        nullptr, nullptr, 0, part, nullptr);

    // 5) combine partials -> per-(row, tile) factors
    softmax_combine<<<BB * SS / 256, 256>>>(part, fac);

    // 6) out = (exp-values * fac) @ vT^T   (flash-style factored softmax)
    mma_gemm_nt<false, false, false, false, true>
        <<<dim3(2, 8, 32), 256, GEMM_SMEM>>>(
        sc, SS2, v, SD, out, SD, SS, DD, 1.f,
        nullptr, nullptr, 0, nullptr, fac);
}

// round 11
// speedup vs baseline: 1.0676x; 1.0141x over previous
#include <cuda_runtime.h>
#include <cstdint>

#define BB 32
#define SS 1024
#define II 128
#define HH 128
#define DD 256   // 2*HH

// ---------------- scratch (static device arrays; allocation-free) -------------
__device__ float g_xg[(size_t)2 * BB * SS * 4 * HH];   // [dir][b][s][4H]
__device__ float g_h [(size_t)BB * SS * DD];           // [b][s][2H] (tf32-rounded)
__device__ float g_qk[(size_t)2 * BB * SS * DD];       // q;k tf32-rounded
__device__ float g_v [(size_t)BB * SS * DD];           // vT [b][d][t] tf32-rounded
__device__ float g_sc[(size_t)BB * SS * SS];           // exp(x - m_tile) values
__device__ float2 g_part[(size_t)BB * SS * 8];         // per-row-tile (m, s)
__device__ float  g_fac [(size_t)BB * SS * 8];         // per-row-tile exp(m_j-m)/l
// staged weights for merged launches
__device__ float g_wqk[(size_t)2 * DD * DD];
__device__ float g_wih[(size_t)2 * 4 * HH * II];
__device__ float g_b1 [2 * 4 * HH];
__device__ float g_b2 [2 * 4 * HH];

// ============================ mma.sync tf32 GEMM =============================
// C[M,N] = alpha * A[M,K] @ B[N,K]^T (+ b1 + b2), fp32 I/O, tf32 compute.
// CTA tile 128x128, 8 warps (2M x 4N), warp tile 64x32, mma m16n8k8.
// 3-stage cp.async pipeline, K chunk 32. Fragments via ldmatrix (x4 A, x2 B).
// PARTIAL: C := exp(alpha*acc - m_tile); emit (m_tile, sum) partials per row.
// SMAX:    A-fragments scaled by per-(row, ktile) factor fac (flash-style).
// =============================================================================
#define GP 36
#define STG_F (128 * GP)
#define STG_B (STG_F * 4)
#define NSTG 3
#define GEMM_SMEM ((2 * NSTG * STG_F + 128 + 1024) * 4)   // 115200 B

__device__ __forceinline__ uint32_t smem_u32(const void* p) {
    uint32_t a;
    asm("{ .reg .u64 t; cvta.to.shared.u64 t, %1; cvt.u32.u64 %0, t; }"
        : "=r"(a) : "l"(p));
    return a;
}
__device__ __forceinline__ void cp16(uint32_t s, const void* g) {
    asm volatile("cp.async.cg.shared.global [%0], [%1], 16;" :: "r"(s), "l"(g));
}
#define CP_COMMIT() asm volatile("cp.async.commit_group;" ::: "memory")
#define CP_WAIT1()  asm volatile("cp.async.wait_group 1;" ::: "memory")
#define CP_WAIT0()  asm volatile("cp.async.wait_group 0;" ::: "memory")

__device__ __forceinline__ uint32_t f2tf(float x) {
    uint32_t r;
    asm("cvt.rna.tf32.f32 %0, %1;" : "=r"(r) : "f"(x));
    return r;
}
__device__ __forceinline__ float roundtf(float x) {
    return __uint_as_float(f2tf(x));
}

__device__ __forceinline__ void ldsm4(uint32_t& r0, uint32_t& r1,
                                      uint32_t& r2, uint32_t& r3,
                                      uint32_t addr) {
    asm volatile("ldmatrix.sync.aligned.m8n8.x4.shared.b16 {%0,%1,%2,%3}, [%4];"
                 : "=r"(r0), "=r"(r1), "=r"(r2), "=r"(r3) : "r"(addr));
}
__device__ __forceinline__ void ldsm2(uint32_t& r0, uint32_t& r1,
                                      uint32_t addr) {
    asm volatile("ldmatrix.sync.aligned.m8n8.x2.shared.b16 {%0,%1}, [%2];"
                 : "=r"(r0), "=r"(r1) : "r"(addr));
}

__device__ __forceinline__ void mma8(float* d, const uint32_t* a,
                                     const uint32_t* b) {
    asm volatile(
        "mma.sync.aligned.m16n8k8.row.col.f32.tf32.tf32.f32 "
        "{%0,%1,%2,%3}, {%4,%5,%6,%7}, {%8,%9}, {%0,%1,%2,%3};"
        : "+f"(d[0]), "+f"(d[1]), "+f"(d[2]), "+f"(d[3])
        : "r"(a[0]), "r"(a[1]), "r"(a[2]), "r"(a[3]), "r"(b[0]), "r"(b[1]));
}

template <bool CVTA, bool CVTB, bool ROUNDC, bool PARTIAL, bool SMAX>
__global__ __launch_bounds__(256, 2) void mma_gemm_nt(
    const float* __restrict__ A, long long sA,
    const float* __restrict__ B, long long sB,
    float* __restrict__ C, long long sC,
    int K, int N, float alpha,
    const float* __restrict__ b1, const float* __restrict__ b2, long long sb,
    float2* __restrict__ part, const float* __restrict__ fac)
{
    extern __shared__ float sm[];
    float* bias   = sm + 2 * NSTG * STG_F;
    float* redm   = bias + 128;            // [128][4]
    float* reds   = redm + 512;            // [128][4]
    const uint32_t smb = smem_u32(sm);

    const int tid  = threadIdx.x;
    const int wid  = tid >> 5, lane = tid & 31;
    const int wm   = wid >> 2, wn = wid & 3;
    const int g    = lane >> 2, tg = lane & 3;

    A += (size_t)blockIdx.z * sA;
    B += (size_t)blockIdx.z * sB;
    C += (size_t)blockIdx.z * sC;
    const int bm = blockIdx.y * 128;
    const int bn = blockIdx.x * 128;

    if (tid < 128) {
        float v = 0.f;
        if (b1) v += b1[blockIdx.z * sb + bn + tid];
        if (b2) v += b2[blockIdx.z * sb + bn + tid];
        bias[tid] = v;
    }

    // ldmatrix lane-address bases (byte offsets relative to stage base)
    // A x4: subs [r0:rows0-7 c0-3][r1:rows8-15 c0-3][r2:rows0-7 c4-7][r3:rows8-15 c4-7]
    uint32_t aBase[4], bBase[4];
    {
        const uint32_t a_lane = ((lane & 15) * GP + ((lane >> 4) << 2)) * 4;
        const uint32_t b_lane = ((lane & 7) * GP + (((lane >> 3) & 1) << 2)) * 4;
#pragma unroll
        for (int mt = 0; mt < 4; mt++)
            aBase[mt] = (uint32_t)((wm * 64 + mt * 16) * GP) * 4 + a_lane;
#pragma unroll
        for (int nt = 0; nt < 4; nt++)
            bBase[nt] = (uint32_t)((wn * 32 + nt * 8) * GP) * 4 + b_lane;
    }

    // SMAX: fac table base for this CTA's 8 row-instances; double-buffered
    const float* facb = nullptr;
    float facA[4][2], facB[4][2];
    if (SMAX) {
        facb = fac + ((size_t)blockIdx.z * SS + bm) * 8;
#pragma unroll
        for (int mt = 0; mt < 4; mt++) {
            facA[mt][0] = facb[(wm * 64 + mt * 16 + g) * 8];
            facA[mt][1] = facb[(wm * 64 + mt * 16 + g + 8) * 8];
        }
    }

    const int lr = tid >> 3;
    const int c4 = tid & 7;
    const float* Ag0 = A + (size_t)bm * K + c4 * 4;
    const float* Bg0 = B + (size_t)bn * K + c4 * 4;

#define LOADCH(ch, st) do {                                                  \
        const uint32_t abase = smb + (uint32_t)(st) * STG_B;                 \
        const uint32_t bbase = smb + (uint32_t)(NSTG + (st)) * STG_B;        \
        const float* Ac = Ag0 + (ch) * 32;                                   \
        const float* Bc = Bg0 + (ch) * 32;                                   \
        _Pragma("unroll")                                                    \
        for (int i = 0; i < 4; i++) {                                        \
            const int row = lr + 32 * i;                                     \
            const uint32_t off = (uint32_t)(row * GP + c4 * 4) * 4;          \
            cp16(abase + off, Ac + (size_t)row * K);                         \
            cp16(bbase + off, Bc + (size_t)row * K);                         \
        } } while (0)

    float acc[4][4][4];
#pragma unroll
    for (int mt = 0; mt < 4; mt++)
#pragma unroll
        for (int nt = 0; nt < 4; nt++)
#pragma unroll
            for (int e = 0; e < 4; e++) acc[mt][nt][e] = 0.f;

    const int nch = K >> 5;
    LOADCH(0, 0); CP_COMMIT();
    LOADCH(1, 1); CP_COMMIT();

    for (int i = 0; i < nch; i++) {
        const int s = i % 3;
        if (i + 2 < nch) CP_WAIT1(); else CP_WAIT0();
        __syncthreads();
        if (i + 2 < nch) { LOADCH(i + 2, (i + 2) % 3); CP_COMMIT(); }

        if (SMAX && (i & 3) == 0) {
            if (i) {
#pragma unroll
                for (int mt = 0; mt < 4; mt++) {
                    facA[mt][0] = facB[mt][0];
                    facA[mt][1] = facB[mt][1];
                }
            }
            if (i + 4 < nch) {            // prefetch next ktile's factors
                const float* fp = facb + (i >> 2) + 1;
#pragma unroll
                for (int mt = 0; mt < 4; mt++) {
                    facB[mt][0] = fp[(wm * 64 + mt * 16 + g) * 8];
                    facB[mt][1] = fp[(wm * 64 + mt * 16 + g + 8) * 8];
                }
            }
        }

        const uint32_t aS = smb + (uint32_t)s * STG_B;
        const uint32_t bS = smb + (uint32_t)(NSTG + s) * STG_B;
#pragma unroll
        for (int ks = 0; ks < 4; ks++) {
            uint32_t af[4][4], bf[4][2];
#pragma unroll
            for (int mt = 0; mt < 4; mt++) {
                ldsm4(af[mt][0], af[mt][1], af[mt][2], af[mt][3],
                      aS + aBase[mt] + ks * 32);
                if (SMAX) {
                    af[mt][0] = f2tf(__uint_as_float(af[mt][0]) * facA[mt][0]);
                    af[mt][1] = f2tf(__uint_as_float(af[mt][1]) * facA[mt][1]);
                    af[mt][2] = f2tf(__uint_as_float(af[mt][2]) * facA[mt][0]);
                    af[mt][3] = f2tf(__uint_as_float(af[mt][3]) * facA[mt][1]);
                } else if (CVTA) {
                    af[mt][0] = f2tf(__uint_as_float(af[mt][0]));
                    af[mt][1] = f2tf(__uint_as_float(af[mt][1]));
                    af[mt][2] = f2tf(__uint_as_float(af[mt][2]));
                    af[mt][3] = f2tf(__uint_as_float(af[mt][3]));
                }
            }
#pragma unroll
            for (int nt = 0; nt < 4; nt++) {
                ldsm2(bf[nt][0], bf[nt][1], bS + bBase[nt] + ks * 32);
                if (CVTB) {
                    bf[nt][0] = f2tf(__uint_as_float(bf[nt][0]));
                    bf[nt][1] = f2tf(__uint_as_float(bf[nt][1]));
                }
            }
#pragma unroll
            for (int mt = 0; mt < 4; mt++)
#pragma unroll
                for (int nt = 0; nt < 4; nt++)
                    mma8(acc[mt][nt], af[mt], bf[nt]);
        }
    }
    __syncthreads();

    if (!PARTIAL) {
        // ---- standard C store ----
#pragma unroll
        for (int mt = 0; mt < 4; mt++) {
            const int r0 = bm + wm * 64 + mt * 16 + g;
#pragma unroll
            for (int nt = 0; nt < 4; nt++) {
                const int cl = wn * 32 + nt * 8 + 2 * tg;
                const int c0 = bn + cl;
                float2 o0, o1;
                o0.x = acc[mt][nt][0] * alpha + bias[cl];
                o0.y = acc[mt][nt][1] * alpha + bias[cl + 1];
                o1.x = acc[mt][nt][2] * alpha + bias[cl];
                o1.y = acc[mt][nt][3] * alpha + bias[cl + 1];
                if (ROUNDC) {
                    o0.x = roundtf(o0.x); o0.y = roundtf(o0.y);
                    o1.x = roundtf(o1.x); o1.y = roundtf(o1.y);
                }
                *(float2*)(C + (size_t)r0 * N + c0)       = o0;
                *(float2*)(C + (size_t)(r0 + 8) * N + c0) = o1;
            }
        }
    } else {
        // ---- fused softmax-partial epilogue ----
        // pass 1: per-row tile max of alpha*acc
#pragma unroll
        for (int mt = 0; mt < 4; mt++)
#pragma unroll
            for (int h2 = 0; h2 < 2; h2++) {
                float lm = -1e30f;
#pragma unroll
                for (int nt = 0; nt < 4; nt++) {
                    lm = fmaxf(lm, acc[mt][nt][h2 * 2 + 0] * alpha);
                    lm = fmaxf(lm, acc[mt][nt][h2 * 2 + 1] * alpha);
                }
                lm = fmaxf(lm, __shfl_xor_sync(0xffffffffu, lm, 1));
                lm = fmaxf(lm, __shfl_xor_sync(0xffffffffu, lm, 2));
                const int r = wm * 64 + mt * 16 + h2 * 8 + g;
                if (tg == 0) redm[r * 4 + wn] = lm;
            }
        __syncthreads();
        // pass 2: exp against tile max; STORE exp values as C; accumulate sum
#pragma unroll
        for (int mt = 0; mt < 4; mt++)
#pragma unroll
            for (int h2 = 0; h2 < 2; h2++) {
                const int r = wm * 64 + mt * 16 + h2 * 8 + g;
                const float m = fmaxf(fmaxf(redm[r * 4 + 0], redm[r * 4 + 1]),
                                      fmaxf(redm[r * 4 + 2], redm[r * 4 + 3]));
                float* Crow = C + (size_t)(bm + r) * N + bn;
                float ls = 0.f;
#pragma unroll
                for (int nt = 0; nt < 4; nt++) {
                    const int cl = wn * 32 + nt * 8 + 2 * tg;
                    float2 e;
                    e.x = __expf(acc[mt][nt][h2 * 2 + 0] * alpha - m);
                    e.y = __expf(acc[mt][nt][h2 * 2 + 1] * alpha - m);
                    *(float2*)(Crow + cl) = e;
                    ls += e.x + e.y;
                }
                ls += __shfl_xor_sync(0xffffffffu, ls, 1);
                ls += __shfl_xor_sync(0xffffffffu, ls, 2);
                if (tg == 0) reds[r * 4 + wn] = ls;
            }
        __syncthreads();
        if (wn == 0 && tg == 0) {
#pragma unroll
            for (int mt = 0; mt < 4; mt++)
#pragma unroll
                for (int h2 = 0; h2 < 2; h2++) {
                    const int r = wm * 64 + mt * 16 + h2 * 8 + g;
                    const float m = fmaxf(fmaxf(redm[r * 4 + 0], redm[r * 4 + 1]),
                                          fmaxf(redm[r * 4 + 2], redm[r * 4 + 3]));
                    const float s = (reds[r * 4 + 0] + reds[r * 4 + 1]) +
                                    (reds[r * 4 + 2] + reds[r * 4 + 3]);
                    part[((size_t)blockIdx.z * SS + bm + r) * 8 + blockIdx.x] =
                        make_float2(m, s);
                }
        }
    }
#undef LOADCH
}

// =============================================================================
// combine split-softmax partials: (m_j, s_j) x8 -> fac_j = exp(m_j - m)/l
// =============================================================================
__global__ __launch_bounds__(256) void softmax_combine(
    const float2* __restrict__ part, float* __restrict__ fac)
{
    const int row = blockIdx.x * 256 + threadIdx.x;
    float2 p[8];
    float m = -1e30f;
#pragma unroll
    for (int j = 0; j < 8; j++) {
        p[j] = part[(size_t)row * 8 + j];
        m = fmaxf(m, p[j].x);
    }
    float l = 0.f;
    float e[8];
#pragma unroll
    for (int j = 0; j < 8; j++) {
        e[j] = __expf(p[j].x - m);
        l += p[j].y * e[j];
    }
    const float inv = 1.f / l;
#pragma unroll
    for (int j = 0; j < 8; j++) fac[(size_t)row * 8 + j] = e[j] * inv;
}

// =============================================================================
// LSTM recurrence (unchanged from R10)
// =============================================================================
#define LSTM_SMEM ((128 + 512) * 4 + 8 * 512 * 16)

__device__ __forceinline__ void fma2(unsigned long long& d,
                                     unsigned long long a,
                                     unsigned long long b)
{
    asm("fma.rn.f32x2 %0, %1, %2, %0;" : "+l"(d) : "l"(a), "l"(b));
}
__device__ __forceinline__ float sum2(unsigned long long a)
{
    return __uint_as_float((unsigned)a) + __uint_as_float((unsigned)(a >> 32));
}
__device__ __forceinline__ float ftanh(float x)
{
    float ax = fabsf(x);
    float e = __expf(2.f * ax);
    float t = 1.f - 2.f / (e + 1.f);
    return copysignf(t, x);
}

__global__ __launch_bounds__(512) void lstm_kernel(
    const float* __restrict__ xg_all,
    const float* __restrict__ Whh_fw,
    const float* __restrict__ Whh_bw,
    float* __restrict__ Hout)
{
    extern __shared__ float sm[];
    float* h_sh = sm;
    float* gate = sm + 128;
    ulonglong2* w_shq = (ulonglong2*)(sm + 640);

    const int dir = blockIdx.x >> 5;
    const int b   = blockIdx.x & 31;
    const int g   = threadIdx.x;
    const float* Whh = dir ? Whh_bw : Whh_fw;

    unsigned long long w2[48];
    {
        const unsigned long long* wr =
            (const unsigned long long*)(Whh + (size_t)g * HH);
#pragma unroll
        for (int i = 0; i < 48; i++) w2[i] = wr[i];
    }
    {
        const ulonglong2* wsrc =
            (const ulonglong2*)(Whh + (size_t)g * HH + 96);
#pragma unroll
        for (int j4 = 0; j4 < 8; j4++) w_shq[j4 * 512 + g] = wsrc[j4];
    }
    if (g < HH) h_sh[g] = 0.f;
    float c = 0.f;
    __syncthreads();

    const float* xg = xg_all + ((size_t)dir * BB + b) * SS * (4 * HH);
    float xg_cur = __ldcs(xg + (size_t)(dir ? SS - 1 : 0) * 512 + g);

    const int gtype = g >> 7;

    for (int t = 0; t < SS; t++) {
        const int s = dir ? (SS - 1 - t) : t;
        float acc = xg_cur;
        if (t + 1 < SS) {
            const int sn = dir ? (SS - 2 - t) : (t + 1);
            xg_cur = __ldcs(xg + (size_t)sn * 512 + g);
        }

        unsigned long long a2a = 0ull, a2b = 0ull;
        const ulonglong2* hq = (const ulonglong2*)h_sh;
#pragma unroll
        for (int i = 0; i < 24; i++) {
            ulonglong2 hv = hq[i];
            fma2(a2a, w2[2 * i], hv.x);
            fma2(a2b, w2[2 * i + 1], hv.y);
        }
#pragma unroll
        for (int j4 = 0; j4 < 8; j4++) {
            ulonglong2 wv = w_shq[j4 * 512 + g];
            ulonglong2 hv = hq[24 + j4];
            fma2(a2a, wv.x, hv.x);
            fma2(a2b, wv.y, hv.y);
        }
        acc += sum2(a2a) + sum2(a2b);

        gate[g] = (gtype == 2) ? ftanh(acc)
                               : 1.f / (1.f + __expf(-acc));
        __syncthreads();

        if (g < HH) {
            const float i_ = gate[g];
            const float f_ = gate[HH + g];
            const float g_ = gate[2 * HH + g];
            const float o_ = gate[3 * HH + g];
            c = f_ * c + i_ * g_;
            const float h = o_ * ftanh(c);
            h_sh[g] = h;
            Hout[((size_t)b * SS + s) * DD + dir * HH + g] = roundtf(h);
        }
        __syncthreads();
    }
}

// =============================================================================
// launch
// =============================================================================
extern "C" void kernel_launch(void* const* d_in, const int* in_sizes, int n_in,
                              void* d_out, int out_size)
{
    const float* x     = (const float*)d_in[0];
    const float* fwWih = (const float*)d_in[1];
    const float* fwWhh = (const float*)d_in[2];
    const float* fwbih = (const float*)d_in[3];
    const float* fwbhh = (const float*)d_in[4];
    const float* bwWih = (const float*)d_in[5];
    const float* bwWhh = (const float*)d_in[6];
    const float* bwbih = (const float*)d_in[7];
    const float* bwbhh = (const float*)d_in[8];
    const float* Wq    = (const float*)d_in[9];
    const float* Wk    = (const float*)d_in[10];
    const float* Wv    = (const float*)d_in[11];
    float* out = (float*)d_out;

    float *xg, *h, *qk, *v, *sc, *fac, *wqk, *wih, *b1s, *b2s;
    float2 *part;
    cudaGetSymbolAddress((void**)&xg,   g_xg);
    cudaGetSymbolAddress((void**)&h,    g_h);
    cudaGetSymbolAddress((void**)&qk,   g_qk);
    cudaGetSymbolAddress((void**)&v,    g_v);
    cudaGetSymbolAddress((void**)&sc,   g_sc);
    cudaGetSymbolAddress((void**)&part, g_part);
    cudaGetSymbolAddress((void**)&fac,  g_fac);
    cudaGetSymbolAddress((void**)&wqk,  g_wqk);
    cudaGetSymbolAddress((void**)&wih,  g_wih);
    cudaGetSymbolAddress((void**)&b1s,  g_b1);
    cudaGetSymbolAddress((void**)&b2s,  g_b2);

    cudaFuncSetAttribute(mma_gemm_nt<true, true, false, false, false>,
                         cudaFuncAttributeMaxDynamicSharedMemorySize, GEMM_SMEM);
    cudaFuncSetAttribute(mma_gemm_nt<false, true, true, false, false>,
                         cudaFuncAttributeMaxDynamicSharedMemorySize, GEMM_SMEM);
    cudaFuncSetAttribute(mma_gemm_nt<true, false, true, false, false>,
                         cudaFuncAttributeMaxDynamicSharedMemorySize, GEMM_SMEM);
    cudaFuncSetAttribute(mma_gemm_nt<false, false, false, true, false>,
                         cudaFuncAttributeMaxDynamicSharedMemorySize, GEMM_SMEM);
    cudaFuncSetAttribute(mma_gemm_nt<false, false, false, false, true>,
                         cudaFuncAttributeMaxDynamicSharedMemorySize, GEMM_SMEM);
    cudaFuncSetAttribute(lstm_kernel,
                         cudaFuncAttributeMaxDynamicSharedMemorySize, LSTM_SMEM);

    const long long SD  = (long long)SS * DD;
    const long long SS2 = (long long)SS * SS;
    const long long BSD = (long long)BB * SS * DD;
    const long long WIH = (long long)4 * HH * II;

    cudaMemcpyAsync(wqk,           Wq,    sizeof(float) * DD * DD,
                    cudaMemcpyDeviceToDevice);
    cudaMemcpyAsync(wqk + DD * DD, Wk,    sizeof(float) * DD * DD,
                    cudaMemcpyDeviceToDevice);
    cudaMemcpyAsync(wih,           fwWih, sizeof(float) * WIH,
                    cudaMemcpyDeviceToDevice);
    cudaMemcpyAsync(wih + WIH,     bwWih, sizeof(float) * WIH,
                    cudaMemcpyDeviceToDevice);
    cudaMemcpyAsync(b1s,           fwbih, sizeof(float) * 4 * HH,
                    cudaMemcpyDeviceToDevice);
    cudaMemcpyAsync(b1s + 4 * HH,  bwbih, sizeof(float) * 4 * HH,
                    cudaMemcpyDeviceToDevice);
    cudaMemcpyAsync(b2s,           fwbhh, sizeof(float) * 4 * HH,
                    cudaMemcpyDeviceToDevice);
    cudaMemcpyAsync(b2s + 4 * HH,  bwbhh, sizeof(float) * 4 * HH,
                    cudaMemcpyDeviceToDevice);

    // 1) xg[dir] = x @ Wih[dir]^T + biases (merged fw/bw)
    mma_gemm_nt<true, true, false, false, false>
        <<<dim3(4, 256, 2), 256, GEMM_SMEM>>>(
        x, 0, wih, WIH, xg, (long long)BB * SS * 4 * HH,
        II, 4 * HH, 1.f, b1s, b2s, 4 * HH, nullptr, nullptr);

    // 2) bidirectional LSTM recurrence -> h [B,S,2H]
    lstm_kernel<<<64, 512, LSTM_SMEM>>>(xg, fwWhh, bwWhh, h);

    // 3) q,k projections merged (z=2)
    mma_gemm_nt<false, true, true, false, false>
        <<<dim3(2, 256, 2), 256, GEMM_SMEM>>>(
        h, 0, wqk, (long long)DD * DD, qk, BSD, DD, DD, 1.f,
        nullptr, nullptr, 0, nullptr, nullptr);

    // 3b) vT = Wv @ h^T
    mma_gemm_nt<true, false, true, false, false>
        <<<dim3(8, 2, 32), 256, GEMM_SMEM>>>(
        Wv, 0, h, SD, v, SD, DD, SS, 1.f, nullptr, nullptr, 0,
        nullptr, nullptr);

    // 4) scores: C = exp(q@k^T/16 - m_tile), partials (m_tile, s_tile)
    mma_gemm_nt<false, false, false, true, false>
        <<<dim3(8, 8, 32), 256, GEMM_SMEM>>>(
        qk, SD, qk + BSD, SD, sc, SS2, DD, SS, 0.0625f,
        nullptr, nullptr, 0, part, nullptr);

    // 5) combine partials -> per-(row, tile) factors
    softmax_combine<<<BB * SS / 256, 256>>>(part, fac);

    // 6) out = (exp-values * fac) @ vT^T   (flash-style factored softmax)
    mma_gemm_nt<false, false, false, false, true>
        <<<dim3(2, 8, 32), 256, GEMM_SMEM>>>(
        sc, SS2, v, SD, out, SD, SS, DD, 1.f,
        nullptr, nullptr, 0, nullptr, fac);
}